// round 7
// baseline (speedup 1.0000x reference)
#include <cuda_runtime.h>

#define DMODEL 1024
#define NHEADS 16
#define DK     64
#define BATCH  4
#define SEQ    2048
#define ROWS   (BATCH*SEQ)    // 8192
#define BH     (BATCH*NHEADS) // 64

// ---------------- scratch ----------------
__device__ float g_q[(size_t)BH*SEQ*DK];
__device__ float g_k[(size_t)BH*SEQ*DK];
__device__ float g_v[(size_t)BH*SEQ*DK];
__device__ float g_ctx[(size_t)ROWS*DMODEL];
__device__ float g_pre[(size_t)ROWS*DMODEL];
__device__ float g_rinv[(size_t)BH*SEQ];

// ---------------- helpers ----------------
__device__ __forceinline__ unsigned f2tf(float f) {
    unsigned u; asm("cvt.rna.tf32.f32 %0, %1;" : "=r"(u) : "f"(f)); return u;
}
__device__ __forceinline__ void mma8(float* c, const unsigned* a, const unsigned* b) {
    asm volatile(
        "mma.sync.aligned.m16n8k8.row.col.f32.tf32.tf32.f32 "
        "{%0,%1,%2,%3}, {%4,%5,%6,%7}, {%8,%9}, {%0,%1,%2,%3};"
        : "+f"(c[0]), "+f"(c[1]), "+f"(c[2]), "+f"(c[3])
        : "r"(a[0]), "r"(a[1]), "r"(a[2]), "r"(a[3]), "r"(b[0]), "r"(b[1]));
}

// Permuted layouts.
// A16 block (16 rows x 8 k) = 128 words; word addr within block = lane*4 + (half + 2*sel)
//   lane = (row&7)*4 + (k&3);  half=(row>>3)&1; sel=(k>>2)&1
//   frag load: LDS.128 at block*128 + lane*4  -> {a0,a1,a2,a3} in mma order.
// B8 block (8 cols x 8 k) = 64 words; word addr = lane*2 + sel
//   lane = (col&7)*4 + (k&3)
//   frag load: LDS.64 at block*64 + lane*2 -> {b0,b1}.

// ---------------- GEMM: C = A(8192x1024) @ W(1024x1024) + bias ----------------
// k-chunk 32: A-perm 8 mblk x 4 ks x 128 w; B-perm 16 nblk x 4 ks x 64 w
#define GEMM_SMEM ((8*4*128 + 16*4*64)*4)

__global__ __launch_bounds__(256, 2) void gemm_tc(
    const float* __restrict__ A, const float* __restrict__ W,
    const float* __restrict__ bias, const float* __restrict__ resid,
    float* __restrict__ out, int mode, float scale)
{
    extern __shared__ unsigned gsm[];
    unsigned* Ap = gsm;                 // [8][4][128]
    unsigned* Bp = Ap + 8*4*128;        // [16][4][64]

    const int tid  = threadIdx.x;
    const int warp = tid >> 5, lane = tid & 31;
    const int wm   = warp >> 2, wn = warp & 3;
    const int brow = blockIdx.y * 128;
    const int bcol = blockIdx.x * 128;

    // staging indices
    const int ar  = tid >> 3;               // 0..31 (rows ar+32j)
    const int ac4 = (tid & 7) * 4;          // k 0..28
    const int aks = ac4 >> 3, asel = (ac4 >> 2) & 1;
    const int wr  = tid >> 5;               // k-row 0..7 (rows wr+8j)
    const int wc4 = (tid & 31) * 4;         // col 0..124
    const int wnb = wc4 >> 3, wg0 = wc4 & 7;
    const int wt  = wr & 3, wsel = (wr >> 2) & 1;

    float c[4][4][4];
    #pragma unroll
    for (int mt = 0; mt < 4; mt++)
        #pragma unroll
        for (int nt = 0; nt < 4; nt++)
            #pragma unroll
            for (int i = 0; i < 4; i++) c[mt][nt][i] = 0.f;

    for (int cc = 0; cc < 32; cc++) {
        int kt = cc * 32;
        // stage A
        #pragma unroll
        for (int j = 0; j < 4; j++) {
            int row = ar + 32*j;
            float4 v = *(const float4*)(A + (size_t)(brow + row)*DMODEL + kt + ac4);
            int mb = row >> 4, half = (row >> 3) & 1, gg = row & 7;
            unsigned* p = Ap + (mb*4 + aks)*128 + gg*16 + half + 2*asel;
            p[0]  = f2tf(v.x); p[4]  = f2tf(v.y);
            p[8]  = f2tf(v.z); p[12] = f2tf(v.w);
        }
        // stage W
        #pragma unroll
        for (int j = 0; j < 4; j++) {
            int k = wr + 8*j;   // ks = j
            float4 v = *(const float4*)(W + (size_t)(kt + k)*DMODEL + bcol + wc4);
            unsigned* p = Bp + (wnb*4 + j)*64 + wg0*8 + wt*2 + wsel;
            p[0]  = f2tf(v.x); p[8]  = f2tf(v.y);
            p[16] = f2tf(v.z); p[24] = f2tf(v.w);
        }
        __syncthreads();

        #pragma unroll
        for (int ks = 0; ks < 4; ks++) {
            unsigned bf[4][2];
            #pragma unroll
            for (int nt = 0; nt < 4; nt++) {
                const uint2 bv = *(const uint2*)(Bp + ((wn*4 + nt)*4 + ks)*64 + lane*2);
                bf[nt][0] = bv.x; bf[nt][1] = bv.y;
            }
            #pragma unroll
            for (int mt = 0; mt < 4; mt++) {
                const uint4 av = *(const uint4*)(Ap + ((wm*4 + mt)*4 + ks)*128 + lane*4);
                unsigned af[4] = {av.x, av.y, av.z, av.w};
                #pragma unroll
                for (int nt = 0; nt < 4; nt++) mma8(c[mt][nt], af, bf[nt]);
            }
        }
        __syncthreads();
    }

    const int g = lane >> 2, t = lane & 3;
    #pragma unroll
    for (int mt = 0; mt < 4; mt++)
        #pragma unroll
        for (int nt = 0; nt < 4; nt++)
            #pragma unroll
            for (int i = 0; i < 4; i++) {
                int row = brow + wm*64 + mt*16 + g + ((i >> 1) ? 8 : 0);
                int col = bcol + wn*32 + nt*8 + 2*t + (i & 1);
                float v = c[mt][nt][i] + bias[col];
                if (mode == 0) {
                    v *= scale;
                    int b = row >> 11, s = row & (SEQ-1);
                    int h = col >> 6,  d = col & (DK-1);
                    out[(size_t)((b*NHEADS + h)*SEQ + s)*DK + d] = v;
                } else {
                    v += resid[(size_t)row*DMODEL + col];
                    out[(size_t)row*DMODEL + col] = v;
                }
            }
}

// ---------------- pass A: row sums of exp(QK^T)*mask ----------------
// Q-perm: 8 mblk x 8 ks x 128 w; K-perm: 8 nblk x 8 ks x 64 w (chunk 64 keys)
#define SUM_SMEM ((8*8*128 + 8*8*64 + SEQ + 512)*4)

__global__ __launch_bounds__(256, 2) void attn_sums(
    const float* __restrict__ Q, const float* __restrict__ K,
    const int* __restrict__ mask, float* __restrict__ rinvg)
{
    extern __shared__ unsigned sm_[];
    unsigned* Qp = sm_;                         // [8][8][128]
    unsigned* Kp = Qp + 8*8*128;                // [8][8][64]
    float*    mskf = (float*)(Kp + 8*8*64);     // [SEQ]
    float*    red  = mskf + SEQ;                // [4][128]

    const int tid  = threadIdx.x;
    const int warp = tid >> 5, lane = tid & 31;
    const int g    = lane >> 2, t = lane & 3;
    const int wm   = warp >> 2, wn = warp & 3;    // 2 x 4
    const int q0   = blockIdx.x * 128;
    const int bh   = blockIdx.y;
    const int b    = bh >> 4;
    const float* Qb = Q + (size_t)bh*SEQ*DK;
    const float* Kb = K + (size_t)bh*SEQ*DK;

    for (int i = tid; i < SEQ; i += 256) mskf[i] = mask[b*SEQ + i] ? 1.f : 0.f;
    #pragma unroll
    for (int j = 0; j < 8; j++) {               // Q 128 x 64 -> A16 perm
        int idx = tid + 256*j;
        int r = idx >> 4, c4 = (idx & 15) * 4;
        float4 v = *(const float4*)(Qb + (size_t)(q0 + r)*DK + c4);
        int mb = r >> 4, half = (r >> 3) & 1, gg = r & 7;
        int ks = c4 >> 3, sel = (c4 >> 2) & 1;
        unsigned* p = Qp + (mb*8 + ks)*128 + gg*16 + half + 2*sel;
        p[0]  = f2tf(v.x); p[4]  = f2tf(v.y);
        p[8]  = f2tf(v.z); p[12] = f2tf(v.w);
    }

    float ps[4][2];
    #pragma unroll
    for (int mt = 0; mt < 4; mt++) { ps[mt][0] = 0.f; ps[mt][1] = 0.f; }

    for (int cc = 0; cc < 32; cc++) {
        int kc = cc * 64;
        __syncthreads();
        #pragma unroll
        for (int j = 0; j < 4; j++) {           // K 64 keys x 64 -> B8 perm
            int idx = tid + 256*j;
            int key = idx >> 4, c4 = (idx & 15) * 4;
            float4 v = *(const float4*)(Kb + (size_t)(kc + key)*DK + c4);
            int nb = key >> 3, gg = key & 7;
            int ks = c4 >> 3, sel = (c4 >> 2) & 1;
            unsigned* p = Kp + (nb*8 + ks)*64 + gg*8 + sel;
            p[0] = f2tf(v.x); p[2] = f2tf(v.y);
            p[4] = f2tf(v.z); p[6] = f2tf(v.w);
        }
        __syncthreads();

        float acc[4][2][4];
        #pragma unroll
        for (int mt = 0; mt < 4; mt++)
            #pragma unroll
            for (int nt = 0; nt < 2; nt++)
                #pragma unroll
                for (int i = 0; i < 4; i++) acc[mt][nt][i] = 0.f;

        #pragma unroll
        for (int ks = 0; ks < 8; ks++) {
            unsigned bf[2][2];
            #pragma unroll
            for (int nt = 0; nt < 2; nt++) {
                const uint2 bv = *(const uint2*)(Kp + ((wn*2 + nt)*8 + ks)*64 + lane*2);
                bf[nt][0] = bv.x; bf[nt][1] = bv.y;
            }
            #pragma unroll
            for (int mt = 0; mt < 4; mt++) {
                const uint4 av = *(const uint4*)(Qp + ((wm*4 + mt)*8 + ks)*128 + lane*4);
                unsigned af[4] = {av.x, av.y, av.z, av.w};
                #pragma unroll
                for (int nt = 0; nt < 2; nt++) mma8(acc[mt][nt], af, bf[nt]);
            }
        }
        #pragma unroll
        for (int mt = 0; mt < 4; mt++)
            #pragma unroll
            for (int nt = 0; nt < 2; nt++)
                #pragma unroll
                for (int half = 0; half < 2; half++) {
                    int col = kc + (wn*2 + nt)*8 + 2*t;
                    ps[mt][half] += __expf(acc[mt][nt][half*2 + 0]) * mskf[col]
                                  + __expf(acc[mt][nt][half*2 + 1]) * mskf[col + 1];
                }
    }

    #pragma unroll
    for (int mt = 0; mt < 4; mt++)
        #pragma unroll
        for (int half = 0; half < 2; half++) {
            float v = ps[mt][half];
            v += __shfl_xor_sync(0xffffffffu, v, 1);
            v += __shfl_xor_sync(0xffffffffu, v, 2);
            if (t == 0) red[wn*128 + wm*64 + mt*16 + g + half*8] = v;
        }
    __syncthreads();
    if (tid < 128) {
        float s = red[tid] + red[128 + tid] + red[256 + tid] + red[384 + tid];
        rinvg[(size_t)bh*SEQ + q0 + tid] = 1.0f / s;
    }
}

// ---------------- pass B: recompute QK, normalize, write att, PV ----------------
// Qp 8x8x128; Kp 8x8x64; Vp 8x8x64; Etf 8x8x128 (A16 over keys); Es [128][68]
#define ESTRF 68
#define FUS_SMEM ((8*8*128 + 8*8*64 + 8*8*64 + 8*8*128 + 128*ESTRF + SEQ + 128)*4)

__global__ __launch_bounds__(512, 1) void attn_fused(
    const float* __restrict__ Q, const float* __restrict__ K, const float* __restrict__ V,
    const int* __restrict__ mask, const float* __restrict__ rinvg,
    float* __restrict__ ctx, float* __restrict__ attout)
{
    extern __shared__ unsigned sm_[];
    unsigned* Qp  = sm_;                          // [8][8][128]
    unsigned* Kp  = Qp + 8*8*128;                 // [8][8][64]
    unsigned* Vp  = Kp + 8*8*64;                  // [8][8][64]
    unsigned* Etf = Vp + 8*8*64;                  // [8][8][128]
    float*    Es  = (float*)(Etf + 8*8*128);      // [128][ESTRF]
    float*    mskf = Es + 128*ESTRF;              // [SEQ]
    float*    rinv = mskf + SEQ;                  // [128]

    const int tid  = threadIdx.x;
    const int warp = tid >> 5, lane = tid & 31;
    const int g    = lane >> 2, t = lane & 3;
    const int wm   = warp >> 2, wn = warp & 3;     // 4 x 4
    const int q0   = blockIdx.x * 128;
    const int bh   = blockIdx.y;
    const int b    = bh >> 4, h = bh & 15;
    const float* Qb = Q + (size_t)bh*SEQ*DK;
    const float* Kb = K + (size_t)bh*SEQ*DK;
    const float* Vb = V + (size_t)bh*SEQ*DK;

    for (int i = tid; i < SEQ; i += 512) mskf[i] = mask[b*SEQ + i] ? 1.f : 0.f;
    if (tid < 128) rinv[tid] = rinvg[(size_t)bh*SEQ + q0 + tid];
    #pragma unroll
    for (int j = 0; j < 4; j++) {                 // Q perm (once)
        int idx = tid + 512*j;
        int r = idx >> 4, c4 = (idx & 15) * 4;
        float4 v = *(const float4*)(Qb + (size_t)(q0 + r)*DK + c4);
        int mb = r >> 4, half = (r >> 3) & 1, gg = r & 7;
        int ks = c4 >> 3, sel = (c4 >> 2) & 1;
        unsigned* p = Qp + (mb*8 + ks)*128 + gg*16 + half + 2*sel;
        p[0]  = f2tf(v.x); p[4]  = f2tf(v.y);
        p[8]  = f2tf(v.z); p[12] = f2tf(v.w);
    }

    float d[2][2][4];
    #pragma unroll
    for (int mt = 0; mt < 2; mt++)
        #pragma unroll
        for (int nt = 0; nt < 2; nt++)
            #pragma unroll
            for (int i = 0; i < 4; i++) d[mt][nt][i] = 0.f;

    for (int cc = 0; cc < 32; cc++) {
        int kc = cc * 64;
        __syncthreads();
        #pragma unroll
        for (int j = 0; j < 2; j++) {             // K perm (keys as B cols)
            int idx = tid + 512*j;
            int key = idx >> 4, c4 = (idx & 15) * 4;
            float4 v = *(const float4*)(Kb + (size_t)(kc + key)*DK + c4);
            int nb = key >> 3, gg = key & 7;
            int ks = c4 >> 3, sel = (c4 >> 2) & 1;
            unsigned* p = Kp + (nb*8 + ks)*64 + gg*8 + sel;
            p[0] = f2tf(v.x); p[2] = f2tf(v.y);
            p[4] = f2tf(v.z); p[6] = f2tf(v.w);
        }
        #pragma unroll
        for (int j = 0; j < 2; j++) {             // V perm (dims as B cols, keys as k)
            int idx = tid + 512*j;
            int key = idx >> 4, c4 = (idx & 15) * 4;
            float4 v = *(const float4*)(Vb + (size_t)(kc + key)*DK + c4);
            int ks = key >> 3, vt = key & 3, sel = (key >> 2) & 1;
            int nb = c4 >> 3, gg0 = c4 & 7;
            unsigned* p = Vp + (nb*8 + ks)*64 + gg0*8 + vt*2 + sel;
            p[0]  = f2tf(v.x); p[8]  = f2tf(v.y);
            p[16] = f2tf(v.z); p[24] = f2tf(v.w);
        }
        __syncthreads();

        // ---- QK ----
        float s[2][2][4];
        #pragma unroll
        for (int mt = 0; mt < 2; mt++)
            #pragma unroll
            for (int nt = 0; nt < 2; nt++)
                #pragma unroll
                for (int i = 0; i < 4; i++) s[mt][nt][i] = 0.f;

        #pragma unroll
        for (int ks = 0; ks < 8; ks++) {
            unsigned bf[2][2];
            #pragma unroll
            for (int nt = 0; nt < 2; nt++) {
                const uint2 bv = *(const uint2*)(Kp + ((wn*2 + nt)*8 + ks)*64 + lane*2);
                bf[nt][0] = bv.x; bf[nt][1] = bv.y;
            }
            #pragma unroll
            for (int mt = 0; mt < 2; mt++) {
                const uint4 av = *(const uint4*)(Qp + ((wm*2 + mt)*8 + ks)*128 + lane*4);
                unsigned af[4] = {av.x, av.y, av.z, av.w};
                #pragma unroll
                for (int nt = 0; nt < 2; nt++) mma8(s[mt][nt], af, bf[nt]);
            }
        }

        // ---- epilogue: normalized exp -> Es (fp32) + Etf (tf32, A16-perm) ----
        #pragma unroll
        for (int mt = 0; mt < 2; mt++)
            #pragma unroll
            for (int nt = 0; nt < 2; nt++)
                #pragma unroll
                for (int half = 0; half < 2; half++) {
                    int row = (wm*2 + mt)*16 + g + half*8;
                    int nb  = wn*2 + nt;
                    int col = nb*8 + 2*t;
                    float iv = rinv[row];
                    float e0 = __expf(s[mt][nt][half*2 + 0]) * mskf[kc + col]     * iv;
                    float e1 = __expf(s[mt][nt][half*2 + 1]) * mskf[kc + col + 1] * iv;
                    *(float2*)(Es + row*ESTRF + col) = make_float2(e0, e1);
                    // Etf: element (row, k=col) in A16 layout over key-dim
                    int mb = wm*2 + mt;
                    int c0 = 2*t, c1 = 2*t + 1;
                    Etf[(mb*8 + nb)*128 + g*16 + (c0 & 3)*4 + half + 2*(c0 >> 2)] = f2tf(e0);
                    Etf[(mb*8 + nb)*128 + g*16 + (c1 & 3)*4 + half + 2*(c1 >> 2)] = f2tf(e1);
                }
        __syncthreads();

        // ---- att write (coalesced float4 from Es) ----
        #pragma unroll
        for (int j = 0; j < 4; j++) {
            int idx = tid + 512*j;
            int r = idx >> 4, c4 = (idx & 15) * 4;
            float4 v = *(const float4*)(Es + r*ESTRF + c4);
            *(float4*)(attout + ((size_t)bh*SEQ + q0 + r)*SEQ + kc + c4) = v;
        }

        // ---- PV ----
        #pragma unroll
        for (int ks = 0; ks < 8; ks++) {
            unsigned bf[2][2];
            #pragma unroll
            for (int nt = 0; nt < 2; nt++) {
                const uint2 bv = *(const uint2*)(Vp + ((wn*2 + nt)*8 + ks)*64 + lane*2);
                bf[nt][0] = bv.x; bf[nt][1] = bv.y;
            }
            #pragma unroll
            for (int mt = 0; mt < 2; mt++) {
                const uint4 av = *(const uint4*)(Etf + ((wm*2 + mt)*8 + ks)*128 + lane*4);
                unsigned af[4] = {av.x, av.y, av.z, av.w};
                #pragma unroll
                for (int nt = 0; nt < 2; nt++) mma8(d[mt][nt], af, bf[nt]);
            }
        }
    }

    #pragma unroll
    for (int mt = 0; mt < 2; mt++)
        #pragma unroll
        for (int nt = 0; nt < 2; nt++)
            #pragma unroll
            for (int half = 0; half < 2; half++) {
                int row = (wm*2 + mt)*16 + g + half*8;
                int col = (wn*2 + nt)*8 + 2*t;
                float2 ov = make_float2(d[mt][nt][half*2 + 0], d[mt][nt][half*2 + 1]);
                *(float2*)(ctx + (size_t)(b*SEQ + q0 + row)*DMODEL + h*DK + col) = ov;
            }
}

// ---------------- LayerNorm ----------------
__global__ __launch_bounds__(256) void ln_kernel(
    const float* __restrict__ pre, const float* __restrict__ gamma,
    const float* __restrict__ beta, float* __restrict__ out)
{
    const int tid = threadIdx.x;
    const int row = blockIdx.x;
    float4 v = ((const float4*)(pre + (size_t)row*DMODEL))[tid];
    float s  = v.x + v.y + v.z + v.w;
    float s2 = v.x*v.x + v.y*v.y + v.z*v.z + v.w*v.w;
    #pragma unroll
    for (int o = 16; o > 0; o >>= 1) {
        s  += __shfl_xor_sync(0xffffffffu, s,  o);
        s2 += __shfl_xor_sync(0xffffffffu, s2, o);
    }
    __shared__ float ws[8], ws2[8];
    __shared__ float mu_s, r_s;
    if ((tid & 31) == 0) { ws[tid >> 5] = s; ws2[tid >> 5] = s2; }
    __syncthreads();
    if (tid == 0) {
        float tt = 0.f, t2 = 0.f;
        #pragma unroll
        for (int i = 0; i < 8; i++) { tt += ws[i]; t2 += ws2[i]; }
        float mu  = tt * (1.0f/DMODEL);
        float var = t2 * (1.0f/DMODEL) - mu*mu;
        mu_s = mu;
        r_s  = rsqrtf(var + 1e-5f);
    }
    __syncthreads();
    float mu = mu_s, r = r_s;
    float4 gm = ((const float4*)gamma)[tid];
    float4 be = ((const float4*)beta)[tid];
    float4 o;
    o.x = (v.x - mu)*r*gm.x + be.x;
    o.y = (v.y - mu)*r*gm.y + be.y;
    o.z = (v.z - mu)*r*gm.z + be.z;
    o.w = (v.w - mu)*r*gm.w + be.w;
    ((float4*)(out + (size_t)row*DMODEL))[tid] = o;
}

// ---------------- launch ----------------
extern "C" void kernel_launch(void* const* d_in, const int* in_sizes, int n_in,
                              void* d_out, int out_size)
{
    const float* x     = (const float*)d_in[0];
    const int*   mask  = (const int*)  d_in[1];
    const float* Wq    = (const float*)d_in[2];
    const float* bq    = (const float*)d_in[3];
    const float* Wk    = (const float*)d_in[4];
    const float* bk    = (const float*)d_in[5];
    const float* Wv    = (const float*)d_in[6];
    const float* bv    = (const float*)d_in[7];
    const float* Wo    = (const float*)d_in[8];
    const float* bo    = (const float*)d_in[9];
    const float* gamma = (const float*)d_in[10];
    const float* beta  = (const float*)d_in[11];
    float* out = (float*)d_out;

    void *pq, *pk, *pv, *pctx, *ppre, *pri;
    cudaGetSymbolAddress(&pq,   g_q);
    cudaGetSymbolAddress(&pk,   g_k);
    cudaGetSymbolAddress(&pv,   g_v);
    cudaGetSymbolAddress(&pctx, g_ctx);
    cudaGetSymbolAddress(&ppre, g_pre);
    cudaGetSymbolAddress(&pri,  g_rinv);

    const long long OUT_ELEMS = (long long)ROWS * DMODEL;
    float* attout = out + OUT_ELEMS;

    cudaFuncSetAttribute(gemm_tc,    cudaFuncAttributeMaxDynamicSharedMemorySize, GEMM_SMEM);
    cudaFuncSetAttribute(attn_sums,  cudaFuncAttributeMaxDynamicSharedMemorySize, SUM_SMEM);
    cudaFuncSetAttribute(attn_fused, cudaFuncAttributeMaxDynamicSharedMemorySize, FUS_SMEM);

    dim3 gg(DMODEL/128, ROWS/128);
    gemm_tc<<<gg, 256, GEMM_SMEM>>>(x, Wq, bq, nullptr, (float*)pq, 0, 0.125f);
    gemm_tc<<<gg, 256, GEMM_SMEM>>>(x, Wk, bk, nullptr, (float*)pk, 0, 1.0f);
    gemm_tc<<<gg, 256, GEMM_SMEM>>>(x, Wv, bv, nullptr, (float*)pv, 0, 1.0f);

    attn_sums<<<dim3(SEQ/128, BH), 256, SUM_SMEM>>>(
        (const float*)pq, (const float*)pk, mask, (float*)pri);
    attn_fused<<<dim3(SEQ/128, BH), 512, FUS_SMEM>>>(
        (const float*)pq, (const float*)pk, (const float*)pv, mask,
        (const float*)pri, (float*)pctx, attout);

    gemm_tc<<<gg, 256, GEMM_SMEM>>>((const float*)pctx, Wo, bo, x, (float*)ppre, 1, 1.0f);
    ln_kernel<<<ROWS, 256>>>((const float*)ppre, gamma, beta, out);
}

// round 8
// speedup vs baseline: 2.8016x; 2.8016x over previous
#include <cuda_runtime.h>
#include <cuda_fp16.h>

#define DMODEL 1024
#define NHEADS 16
#define DK     64
#define BATCH  4
#define SEQ    2048
#define ROWS   (BATCH*SEQ)    // 8192
#define BH     (BATCH*NHEADS) // 64

// ---------------- scratch ----------------
__device__ float g_q[(size_t)BH*SEQ*DK];
__device__ float g_k[(size_t)BH*SEQ*DK];
__device__ float g_v[(size_t)BH*SEQ*DK];
__device__ float g_ctx[(size_t)ROWS*DMODEL];
__device__ float g_pre[(size_t)ROWS*DMODEL];
__device__ float g_rinv[(size_t)BH*SEQ];

// ---------------- helpers ----------------
__device__ __forceinline__ unsigned f2h2(float a, float b) {
    __half2 h = __floats2half2_rn(a, b);
    return *(unsigned*)&h;
}
__device__ __forceinline__ void mma16(float* c, const unsigned* a, const unsigned* b) {
    asm volatile(
        "mma.sync.aligned.m16n8k16.row.col.f32.f16.f16.f32 "
        "{%0,%1,%2,%3}, {%4,%5,%6,%7}, {%8,%9}, {%0,%1,%2,%3};"
        : "+f"(c[0]), "+f"(c[1]), "+f"(c[2]), "+f"(c[3])
        : "r"(a[0]), "r"(a[1]), "r"(a[2]), "r"(a[3]), "r"(b[0]), "r"(b[1]));
}

// ---------------- GEMM: C = A(8192x1024) @ W(1024x1024) + bias ----------------
// k-chunk 32 = 16 half2 words. As [128][20], Bs(kpair-major) [16][136]
#define APSTR 20
#define BPSTR 136
#define GEMM_SMEM ((128*APSTR + 16*BPSTR)*4)

__global__ __launch_bounds__(256, 2) void gemm_tc(
    const float* __restrict__ A, const float* __restrict__ W,
    const float* __restrict__ bias, const float* __restrict__ resid,
    float* __restrict__ out, int mode, float scale)
{
    extern __shared__ unsigned gsm[];
    unsigned* As = gsm;                 // [128][APSTR] half2 (k-pairs)
    unsigned* Bs = As + 128*APSTR;      // [16][BPSTR]  half2 {W[2kp][c],W[2kp+1][c]}

    const int tid  = threadIdx.x;
    const int warp = tid >> 5, lane = tid & 31;
    const int g    = lane >> 2, t = lane & 3;
    const int wm   = warp >> 2, wn = warp & 3;
    const int brow = blockIdx.y * 128;
    const int bcol = blockIdx.x * 128;

    float c[4][4][4];
    #pragma unroll
    for (int mt = 0; mt < 4; mt++)
        #pragma unroll
        for (int nt = 0; nt < 4; nt++)
            #pragma unroll
            for (int i = 0; i < 4; i++) c[mt][nt][i] = 0.f;

    for (int cc = 0; cc < 32; cc++) {
        int kt = cc * 32;
        // stage A: 128 rows x 32 k
        #pragma unroll
        for (int j = 0; j < 4; j++) {
            int idx = tid + 256*j;
            int r = idx >> 3, c4 = (idx & 7) * 4, kp0 = (idx & 7) * 2;
            float4 v = *(const float4*)(A + (size_t)(brow + r)*DMODEL + kt + c4);
            As[r*APSTR + kp0    ] = f2h2(v.x, v.y);
            As[r*APSTR + kp0 + 1] = f2h2(v.z, v.w);
        }
        // stage W: pack k-pairs across rows
        #pragma unroll
        for (int j = 0; j < 2; j++) {
            int idx = tid + 256*j;
            int kp = idx >> 5, c4 = (idx & 31) * 4;
            float4 v0 = *(const float4*)(W + (size_t)(kt + 2*kp    )*DMODEL + bcol + c4);
            float4 v1 = *(const float4*)(W + (size_t)(kt + 2*kp + 1)*DMODEL + bcol + c4);
            unsigned* p = Bs + kp*BPSTR + c4;
            p[0] = f2h2(v0.x, v1.x); p[1] = f2h2(v0.y, v1.y);
            p[2] = f2h2(v0.z, v1.z); p[3] = f2h2(v0.w, v1.w);
        }
        __syncthreads();

        #pragma unroll
        for (int ks = 0; ks < 2; ks++) {
            int k0 = ks*8;                      // half2-word units (16 k)
            unsigned bf[4][2];
            #pragma unroll
            for (int nt = 0; nt < 4; nt++) {
                int col = wn*32 + nt*8 + g;
                bf[nt][0] = Bs[(k0 + t    )*BPSTR + col];
                bf[nt][1] = Bs[(k0 + t + 4)*BPSTR + col];
            }
            #pragma unroll
            for (int mt = 0; mt < 4; mt++) {
                int r0 = wm*64 + mt*16 + g;
                unsigned af[4] = {As[r0*APSTR + k0 + t], As[(r0+8)*APSTR + k0 + t],
                                  As[r0*APSTR + k0 + t + 4], As[(r0+8)*APSTR + k0 + t + 4]};
                #pragma unroll
                for (int nt = 0; nt < 4; nt++) mma16(c[mt][nt], af, bf[nt]);
            }
        }
        __syncthreads();
    }

    #pragma unroll
    for (int mt = 0; mt < 4; mt++)
        #pragma unroll
        for (int nt = 0; nt < 4; nt++)
            #pragma unroll
            for (int i = 0; i < 4; i++) {
                int row = brow + wm*64 + mt*16 + g + ((i >> 1) ? 8 : 0);
                int col = bcol + wn*32 + nt*8 + 2*t + (i & 1);
                float v = c[mt][nt][i] + bias[col];
                if (mode == 0) {
                    v *= scale;
                    int b = row >> 11, s = row & (SEQ-1);
                    int h = col >> 6,  d = col & (DK-1);
                    out[(size_t)((b*NHEADS + h)*SEQ + s)*DK + d] = v;
                } else {
                    v += resid[(size_t)row*DMODEL + col];
                    out[(size_t)row*DMODEL + col] = v;
                }
            }
}

// ---------------- pass A: row sums of exp(QK^T)*mask ----------------
// Qs [128][36] half2, Ks [128][36] half2, chunk 128 keys
#define QPSTR 36
#define SUM_SMEM ((128*QPSTR + 128*QPSTR + SEQ + 512)*4)

__global__ __launch_bounds__(256, 2) void attn_sums(
    const float* __restrict__ Q, const float* __restrict__ K,
    const int* __restrict__ mask, float* __restrict__ rinvg)
{
    extern __shared__ unsigned sm_[];
    unsigned* Qs  = sm_;                          // [128][QPSTR]
    unsigned* Ks  = Qs + 128*QPSTR;               // [128][QPSTR]
    float*    mskf = (float*)(Ks + 128*QPSTR);    // [SEQ]
    float*    red  = mskf + SEQ;                  // [4][128]

    const int tid  = threadIdx.x;
    const int warp = tid >> 5, lane = tid & 31;
    const int g    = lane >> 2, t = lane & 3;
    const int wm   = warp >> 2, wn = warp & 3;    // 2 x 4
    const int q0   = blockIdx.x * 128;
    const int bh   = blockIdx.y;
    const int b    = bh >> 4;
    const float* Qb = Q + (size_t)bh*SEQ*DK;
    const float* Kb = K + (size_t)bh*SEQ*DK;

    for (int i = tid; i < SEQ; i += 256) mskf[i] = mask[b*SEQ + i] ? 1.f : 0.f;
    #pragma unroll
    for (int j = 0; j < 4; j++) {                 // Q 128 x 64
        int idx = tid + 256*j;
        int r = idx >> 3, c4 = ((idx & 7) & 3) * 0; // placeholder (recomputed below)
        (void)c4;
        int cof = (idx & 7) * 8;                  // not used
        (void)cof;
        // proper: 128 rows x 16 float4 per row? DK=64 -> 16 floats4 per row? 64/4=16.
        // tasks = 128*16 = 2048 -> 8 per thread. Redo below.
        break;
    }
    // Q staging: 128 rows x 16 float4 = 2048 tasks, 8 per thread
    #pragma unroll
    for (int j = 0; j < 8; j++) {
        int idx = tid + 256*j;
        int r = idx >> 4, c4 = (idx & 15) * 4, kp0 = (idx & 15) * 2;
        float4 v = *(const float4*)(Qb + (size_t)(q0 + r)*DK + c4);
        Qs[r*QPSTR + kp0    ] = f2h2(v.x, v.y);
        Qs[r*QPSTR + kp0 + 1] = f2h2(v.z, v.w);
    }

    float ps[4][2];
    #pragma unroll
    for (int mt = 0; mt < 4; mt++) { ps[mt][0] = 0.f; ps[mt][1] = 0.f; }

    for (int cc = 0; cc < 16; cc++) {
        int kc = cc * 128;
        __syncthreads();
        #pragma unroll
        for (int j = 0; j < 8; j++) {             // K 128 keys x 64
            int idx = tid + 256*j;
            int r = idx >> 4, c4 = (idx & 15) * 4, kp0 = (idx & 15) * 2;
            float4 v = *(const float4*)(Kb + (size_t)(kc + r)*DK + c4);
            Ks[r*QPSTR + kp0    ] = f2h2(v.x, v.y);
            Ks[r*QPSTR + kp0 + 1] = f2h2(v.z, v.w);
        }
        __syncthreads();

        float acc[4][4][4];
        #pragma unroll
        for (int mt = 0; mt < 4; mt++)
            #pragma unroll
            for (int nt = 0; nt < 4; nt++)
                #pragma unroll
                for (int i = 0; i < 4; i++) acc[mt][nt][i] = 0.f;

        #pragma unroll
        for (int ks = 0; ks < 4; ks++) {
            int k0 = ks*8;
            unsigned bf[4][2];
            #pragma unroll
            for (int nt = 0; nt < 4; nt++) {
                int col = wn*32 + nt*8 + g;
                bf[nt][0] = Ks[col*QPSTR + k0 + t];
                bf[nt][1] = Ks[col*QPSTR + k0 + t + 4];
            }
            #pragma unroll
            for (int mt = 0; mt < 4; mt++) {
                int r0 = wm*64 + mt*16 + g;
                unsigned af[4] = {Qs[r0*QPSTR + k0 + t], Qs[(r0+8)*QPSTR + k0 + t],
                                  Qs[r0*QPSTR + k0 + t + 4], Qs[(r0+8)*QPSTR + k0 + t + 4]};
                #pragma unroll
                for (int nt = 0; nt < 4; nt++) mma16(acc[mt][nt], af, bf[nt]);
            }
        }
        #pragma unroll
        for (int mt = 0; mt < 4; mt++)
            #pragma unroll
            for (int nt = 0; nt < 4; nt++)
                #pragma unroll
                for (int half = 0; half < 2; half++) {
                    int col = kc + wn*32 + nt*8 + 2*t;
                    ps[mt][half] += __expf(acc[mt][nt][half*2 + 0]) * mskf[col]
                                  + __expf(acc[mt][nt][half*2 + 1]) * mskf[col + 1];
                }
    }

    #pragma unroll
    for (int mt = 0; mt < 4; mt++)
        #pragma unroll
        for (int half = 0; half < 2; half++) {
            float v = ps[mt][half];
            v += __shfl_xor_sync(0xffffffffu, v, 1);
            v += __shfl_xor_sync(0xffffffffu, v, 2);
            if (t == 0) red[wn*128 + wm*64 + mt*16 + g + half*8] = v;
        }
    __syncthreads();
    if (tid < 128) {
        float s = red[tid] + red[128 + tid] + red[256 + tid] + red[384 + tid];
        rinvg[(size_t)bh*SEQ + q0 + tid] = 1.0f / s;
    }
}

// ---------------- pass B: recompute QK, normalize, write att, PV ----------------
// Qs[128][36], Kp[64][36], Vp[32][72] (kp-major), Etf[128][36], Es[128][68] fp32
#define VPSTR 72
#define ESTRF 68
#define FUS_SMEM ((128*QPSTR + 64*QPSTR + 32*VPSTR + 128*QPSTR + 128*ESTRF + SEQ + 128)*4)

__global__ __launch_bounds__(512, 1) void attn_fused(
    const float* __restrict__ Q, const float* __restrict__ K, const float* __restrict__ V,
    const int* __restrict__ mask, const float* __restrict__ rinvg,
    float* __restrict__ ctx, float* __restrict__ attout)
{
    extern __shared__ unsigned sm_[];
    unsigned* Qs  = sm_;                          // [128][QPSTR]
    unsigned* Kp  = Qs + 128*QPSTR;               // [64][QPSTR]
    unsigned* Vp  = Kp + 64*QPSTR;                // [32][VPSTR] kp-major over keys
    unsigned* Etf = Vp + 32*VPSTR;                // [128][QPSTR] E half2 (key-pairs)
    float*    Es  = (float*)(Etf + 128*QPSTR);    // [128][ESTRF]
    float*    mskf = Es + 128*ESTRF;              // [SEQ]
    float*    rinv = mskf + SEQ;                  // [128]

    const int tid  = threadIdx.x;
    const int warp = tid >> 5, lane = tid & 31;
    const int g    = lane >> 2, t = lane & 3;
    const int wm   = warp >> 2, wn = warp & 3;     // 4 x 4
    const int q0   = blockIdx.x * 128;
    const int bh   = blockIdx.y;
    const int b    = bh >> 4, h = bh & 15;
    const float* Qb = Q + (size_t)bh*SEQ*DK;
    const float* Kb = K + (size_t)bh*SEQ*DK;
    const float* Vb = V + (size_t)bh*SEQ*DK;

    for (int i = tid; i < SEQ; i += 512) mskf[i] = mask[b*SEQ + i] ? 1.f : 0.f;
    if (tid < 128) rinv[tid] = rinvg[(size_t)bh*SEQ + q0 + tid];
    #pragma unroll
    for (int j = 0; j < 4; j++) {                  // Q 128 rows x 16 float4
        int idx = tid + 512*j;
        int r = idx >> 4, c4 = (idx & 15) * 4, kp0 = (idx & 15) * 2;
        float4 v = *(const float4*)(Qb + (size_t)(q0 + r)*DK + c4);
        Qs[r*QPSTR + kp0    ] = f2h2(v.x, v.y);
        Qs[r*QPSTR + kp0 + 1] = f2h2(v.z, v.w);
    }

    float d[2][2][4];
    #pragma unroll
    for (int mt = 0; mt < 2; mt++)
        #pragma unroll
        for (int nt = 0; nt < 2; nt++)
            #pragma unroll
            for (int i = 0; i < 4; i++) d[mt][nt][i] = 0.f;

    for (int cc = 0; cc < 32; cc++) {
        int kc = cc * 64;
        __syncthreads();                            // prev PV done (Kp/Vp/Etf reusable)
        {                                           // K: 64 keys x 16 float4 = 1024, 2/thr
            #pragma unroll
            for (int j = 0; j < 2; j++) {
                int idx = tid + 512*j;
                int r = idx >> 4, c4 = (idx & 15) * 4, kp0 = (idx & 15) * 2;
                float4 v = *(const float4*)(Kb + (size_t)(kc + r)*DK + c4);
                Kp[r*QPSTR + kp0    ] = f2h2(v.x, v.y);
                Kp[r*QPSTR + kp0 + 1] = f2h2(v.z, v.w);
            }
            // V: kp(0..31) x col4(0..15) = 512 tasks, 1/thr
            int kp = tid >> 4, c4 = (tid & 15) * 4;
            float4 v0 = *(const float4*)(Vb + (size_t)(kc + 2*kp    )*DK + c4);
            float4 v1 = *(const float4*)(Vb + (size_t)(kc + 2*kp + 1)*DK + c4);
            unsigned* p = Vp + kp*VPSTR + c4;
            p[0] = f2h2(v0.x, v1.x); p[1] = f2h2(v0.y, v1.y);
            p[2] = f2h2(v0.z, v1.z); p[3] = f2h2(v0.w, v1.w);
        }
        __syncthreads();

        // ---- QK (same chain order as attn_sums) ----
        float s[2][2][4];
        #pragma unroll
        for (int mt = 0; mt < 2; mt++)
            #pragma unroll
            for (int nt = 0; nt < 2; nt++)
                #pragma unroll
                for (int i = 0; i < 4; i++) s[mt][nt][i] = 0.f;

        #pragma unroll
        for (int ks = 0; ks < 4; ks++) {
            int k0 = ks*8;
            unsigned bf[2][2];
            #pragma unroll
            for (int nt = 0; nt < 2; nt++) {
                int col = wn*16 + nt*8 + g;
                bf[nt][0] = Kp[col*QPSTR + k0 + t];
                bf[nt][1] = Kp[col*QPSTR + k0 + t + 4];
            }
            #pragma unroll
            for (int mt = 0; mt < 2; mt++) {
                int r0 = wm*32 + mt*16 + g;
                unsigned af[4] = {Qs[r0*QPSTR + k0 + t], Qs[(r0+8)*QPSTR + k0 + t],
                                  Qs[r0*QPSTR + k0 + t + 4], Qs[(r0+8)*QPSTR + k0 + t + 4]};
                #pragma unroll
                for (int nt = 0; nt < 2; nt++) mma16(s[mt][nt], af, bf[nt]);
            }
        }

        // ---- epilogue: normalized exp -> Es (fp32) + Etf (half2 key-pairs) ----
        #pragma unroll
        for (int mt = 0; mt < 2; mt++)
            #pragma unroll
            for (int nt = 0; nt < 2; nt++)
                #pragma unroll
                for (int half = 0; half < 2; half++) {
                    int row = wm*32 + mt*16 + g + half*8;
                    int nb  = wn*2 + nt;
                    int col = nb*8 + 2*t;
                    float iv = rinv[row];
                    float e0 = __expf(s[mt][nt][half*2 + 0]) * mskf[kc + col]     * iv;
                    float e1 = __expf(s[mt][nt][half*2 + 1]) * mskf[kc + col + 1] * iv;
                    *(float2*)(Es + row*ESTRF + col) = make_float2(e0, e1);
                    Etf[row*QPSTR + nb*4 + t] = f2h2(e0, e1);
                }
        __syncthreads();

        // ---- att write ----
        #pragma unroll
        for (int j = 0; j < 4; j++) {
            int idx = tid + 512*j;
            int r = idx >> 4, c4 = (idx & 15) * 4;
            float4 v = *(const float4*)(Es + r*ESTRF + c4);
            *(float4*)(attout + ((size_t)bh*SEQ + q0 + r)*SEQ + kc + c4) = v;
        }

        // ---- PV ----
        #pragma unroll
        for (int ks = 0; ks < 4; ks++) {
            int k0 = ks*8;                          // key-pair units
            unsigned bf[2][2];
            #pragma unroll
            for (int nt = 0; nt < 2; nt++) {
                int col = wn*16 + nt*8 + g;
                bf[nt][0] = Vp[(k0 + t)*VPSTR + col];
                bf[nt][1] = Vp[(k0 + t + 4)*VPSTR + col];
            }
            #pragma unroll
            for (int mt = 0; mt < 2; mt++) {
                int r0 = wm*32 + mt*16 + g;
                unsigned af[4] = {Etf[r0*QPSTR + k0 + t], Etf[(r0+8)*QPSTR + k0 + t],
                                  Etf[r0*QPSTR + k0 + t + 4], Etf[(r0+8)*QPSTR + k0 + t + 4]};
                #pragma unroll
                for (int nt = 0; nt < 2; nt++) mma16(d[mt][nt], af, bf[nt]);
            }
        }
    }

    #pragma unroll
    for (int mt = 0; mt < 2; mt++)
        #pragma unroll
        for (int nt = 0; nt < 2; nt++)
            #pragma unroll
            for (int half = 0; half < 2; half++) {
                int row = wm*32 + mt*16 + g + half*8;
                int col = wn*16 + nt*8 + 2*t;
                float2 ov = make_float2(d[mt][nt][half*2 + 0], d[mt][nt][half*2 + 1]);
                *(float2*)(ctx + (size_t)(b*SEQ + q0 + row)*DMODEL + h*DK + col) = ov;
            }
}

// ---------------- LayerNorm ----------------
__global__ __launch_bounds__(256) void ln_kernel(
    const float* __restrict__ pre, const float* __restrict__ gamma,
    const float* __restrict__ beta, float* __restrict__ out)
{
    const int tid = threadIdx.x;
    const int row = blockIdx.x;
    float4 v = ((const float4*)(pre + (size_t)row*DMODEL))[tid];
    float s  = v.x + v.y + v.z + v.w;
    float s2 = v.x*v.x + v.y*v.y + v.z*v.z + v.w*v.w;
    #pragma unroll
    for (int o = 16; o > 0; o >>= 1) {
        s  += __shfl_xor_sync(0xffffffffu, s,  o);
        s2 += __shfl_xor_sync(0xffffffffu, s2, o);
    }
    __shared__ float ws[8], ws2[8];
    __shared__ float mu_s, r_s;
    if ((tid & 31) == 0) { ws[tid >> 5] = s; ws2[tid >> 5] = s2; }
    __syncthreads();
    if (tid == 0) {
        float tt = 0.f, t2 = 0.f;
        #pragma unroll
        for (int i = 0; i < 8; i++) { tt += ws[i]; t2 += ws2[i]; }
        float mu  = tt * (1.0f/DMODEL);
        float var = t2 * (1.0f/DMODEL) - mu*mu;
        mu_s = mu;
        r_s  = rsqrtf(var + 1e-5f);
    }
    __syncthreads();
    float mu = mu_s, r = r_s;
    float4 gm = ((const float4*)gamma)[tid];
    float4 be = ((const float4*)beta)[tid];
    float4 o;
    o.x = (v.x - mu)*r*gm.x + be.x;
    o.y = (v.y - mu)*r*gm.y + be.y;
    o.z = (v.z - mu)*r*gm.z + be.z;
    o.w = (v.w - mu)*r*gm.w + be.w;
    ((float4*)(out + (size_t)row*DMODEL))[tid] = o;
}

// ---------------- launch ----------------
extern "C" void kernel_launch(void* const* d_in, const int* in_sizes, int n_in,
                              void* d_out, int out_size)
{
    const float* x     = (const float*)d_in[0];
    const int*   mask  = (const int*)  d_in[1];
    const float* Wq    = (const float*)d_in[2];
    const float* bq    = (const float*)d_in[3];
    const float* Wk    = (const float*)d_in[4];
    const float* bk    = (const float*)d_in[5];
    const float* Wv    = (const float*)d_in[6];
    const float* bv    = (const float*)d_in[7];
    const float* Wo    = (const float*)d_in[8];
    const float* bo    = (const float*)d_in[9];
    const float* gamma = (const float*)d_in[10];
    const float* beta  = (const float*)d_in[11];
    float* out = (float*)d_out;

    void *pq, *pk, *pv, *pctx, *ppre, *pri;
    cudaGetSymbolAddress(&pq,   g_q);
    cudaGetSymbolAddress(&pk,   g_k);
    cudaGetSymbolAddress(&pv,   g_v);
    cudaGetSymbolAddress(&pctx, g_ctx);
    cudaGetSymbolAddress(&ppre, g_pre);
    cudaGetSymbolAddress(&pri,  g_rinv);

    const long long OUT_ELEMS = (long long)ROWS * DMODEL;
    float* attout = out + OUT_ELEMS;

    cudaFuncSetAttribute(gemm_tc,    cudaFuncAttributeMaxDynamicSharedMemorySize, GEMM_SMEM);
    cudaFuncSetAttribute(attn_sums,  cudaFuncAttributeMaxDynamicSharedMemorySize, SUM_SMEM);
    cudaFuncSetAttribute(attn_fused, cudaFuncAttributeMaxDynamicSharedMemorySize, FUS_SMEM);

    dim3 gg(DMODEL/128, ROWS/128);
    gemm_tc<<<gg, 256, GEMM_SMEM>>>(x, Wq, bq, nullptr, (float*)pq, 0, 0.125f);
    gemm_tc<<<gg, 256, GEMM_SMEM>>>(x, Wk, bk, nullptr, (float*)pk, 0, 1.0f);
    gemm_tc<<<gg, 256, GEMM_SMEM>>>(x, Wv, bv, nullptr, (float*)pv, 0, 1.0f);

    attn_sums<<<dim3(SEQ/128, BH), 256, SUM_SMEM>>>(
        (const float*)pq, (const float*)pk, mask, (float*)pri);
    attn_fused<<<dim3(SEQ/128, BH), 512, FUS_SMEM>>>(
        (const float*)pq, (const float*)pk, (const float*)pv, mask,
        (const float*)pri, (float*)pctx, attout);

    gemm_tc<<<gg, 256, GEMM_SMEM>>>((const float*)pctx, Wo, bo, x, (float*)ppre, 1, 1.0f);
    ln_kernel<<<ROWS, 256>>>((const float*)ppre, gamma, beta, out);
}